// round 7
// baseline (speedup 1.0000x reference)
#include <cuda_runtime.h>
#include <cstdint>

#define N_NODES 50000
#define N_EDGES 800000
#define D_IN    256
#define D_OUT   64
#define NEG_SLOPE 0.2f

// Scratch: support = x @ W^T + b   [N_NODES, D_OUT]
__device__ float g_support[N_NODES * D_OUT];
// CSR row pointers for sorted edge_dst
__device__ int g_rowptr[N_NODES + 1];
// W tf32 splits in fragment-paired layout: [n][kb][tq] -> uint2{w[kb*8+tq], w[kb*8+tq+4]}
__device__ uint2 g_whp[D_OUT * (D_IN / 8) * 4];   // 8192 uint2
__device__ uint2 g_wlp[D_OUT * (D_IN / 8) * 4];

// ---------------------------------------------------------------------------
// TF32 helpers
// ---------------------------------------------------------------------------
__device__ __forceinline__ void tf32_split(float f, uint32_t& hi, uint32_t& lo) {
    uint32_t h;
    asm("cvt.rna.tf32.f32 %0, %1;" : "=r"(h) : "f"(f));
    float hf = __uint_as_float(h);
    float lf = f - hf;
    asm("cvt.rna.tf32.f32 %0, %1;" : "=r"(lo) : "f"(lf));
    hi = h;
}

__device__ __forceinline__ void mma_tf32(float c[4], const uint32_t a[4], uint32_t b0, uint32_t b1) {
    asm volatile(
        "mma.sync.aligned.m16n8k8.row.col.f32.tf32.tf32.f32 "
        "{%0,%1,%2,%3}, {%4,%5,%6,%7}, {%8,%9}, {%0,%1,%2,%3};"
        : "+f"(c[0]), "+f"(c[1]), "+f"(c[2]), "+f"(c[3])
        : "r"(a[0]), "r"(a[1]), "r"(a[2]), "r"(a[3]), "r"(b0), "r"(b1));
}

// ---------------------------------------------------------------------------
// Kernel 0a: W tf32 split into fragment-paired layout (8192 threads, tiny)
// ---------------------------------------------------------------------------
__global__ void wsplit_kernel(const float* __restrict__ W,
                              uint2* __restrict__ whp,
                              uint2* __restrict__ wlp) {
    int e = blockIdx.x * blockDim.x + threadIdx.x;
    if (e >= D_OUT * (D_IN / 8) * 4) return;
    int n   = e >> 7;        // 0..63
    int rem = e & 127;
    int kb  = rem >> 2;      // 0..31
    int tq  = rem & 3;       // 0..3
    float w0 = __ldg(&W[n * D_IN + kb * 8 + tq]);
    float w1 = __ldg(&W[n * D_IN + kb * 8 + tq + 4]);
    uint32_t h0, l0, h1, l1;
    tf32_split(w0, h0, l0);
    tf32_split(w1, h1, l1);
    whp[e] = make_uint2(h0, h1);
    wlp[e] = make_uint2(l0, l1);
}

// ---------------------------------------------------------------------------
// Kernel 0b: vectorized CSR rowptr from sorted edge_dst (thread per 4 edges)
// ---------------------------------------------------------------------------
__global__ void rowptr4_kernel(const int* __restrict__ edge_dst,
                               int* __restrict__ rowptr) {
    int i = blockIdx.x * blockDim.x + threadIdx.x;   // quad index
    if (i >= N_EDGES / 4) return;
    const int e0 = i * 4;
    int4 d = __ldg((const int4*)&edge_dst[e0]);
    int prev;
    if (e0 == 0) {
        prev = -1;   // fill 0..d.x with 0
    } else {
        prev = __ldg(&edge_dst[e0 - 1]);
    }
    int dd[4] = {d.x, d.y, d.z, d.w};
    #pragma unroll
    for (int j = 0; j < 4; j++) {
        for (int n = prev + 1; n <= dd[j]; n++) rowptr[n] = e0 + j;
        prev = dd[j];
    }
    if (e0 + 4 == N_EDGES) {
        for (int n = prev + 1; n <= N_NODES; n++) rowptr[n] = N_EDGES;
    }
}

// ---------------------------------------------------------------------------
// Kernel 1: support = x @ W^T + b  via tf32 tensor cores (3xTF32)
//   Block: 128 threads (4 warps), 128 rows. Warp: 32 rows (two m16 tiles) x 64 cols.
// ---------------------------------------------------------------------------
#define KC 16

__global__ __launch_bounds__(128) void gemm_tf32_kernel(
    const float* __restrict__ x,
    const uint2* __restrict__ whp,
    const uint2* __restrict__ wlp,
    const float* __restrict__ bias,
    float* __restrict__ support)
{
    __shared__ float xs[128][20];     // [row][k], stride 20 -> conflict-free frag reads
    __shared__ uint2 wh_s[64][12];    // [n][kbl*4+tq], stride 12 uint2
    __shared__ uint2 wl_s[64][12];

    const int tid  = threadIdx.x;
    const int warp = tid >> 5;    // 0..3
    const int lane = tid & 31;
    const int gq   = lane >> 2;   // 0..7
    const int tq   = lane & 3;    // 0..3
    const int row_base = blockIdx.x * 128;

    float acc[2][8][4];
    #pragma unroll
    for (int t = 0; t < 2; t++)
        #pragma unroll
        for (int nt = 0; nt < 8; nt++)
            #pragma unroll
            for (int j = 0; j < 4; j++) acc[t][nt][j] = 0.f;

    for (int kt = 0; kt < D_IN; kt += KC) {
        const int kb0 = kt >> 3;
        #pragma unroll
        for (int i = 0; i < 4; i++) {
            int idx = tid + i * 128;
            int r   = idx >> 2;
            int c4  = idx & 3;
            int gr  = row_base + r;
            float4 v = make_float4(0.f, 0.f, 0.f, 0.f);
            if (gr < N_NODES)
                v = *(const float4*)&x[(size_t)gr * D_IN + kt + c4 * 4];
            *(float4*)&xs[r][c4 * 4] = v;
        }
        #pragma unroll
        for (int i = 0; i < 2; i++) {
            int idx = tid + i * 128;
            int n   = idx >> 2;
            int q   = idx & 3;
            ((uint4*)&wh_s[n][0])[q] = ((const uint4*)whp)[n * 64 + kb0 * 2 + q];
            ((uint4*)&wl_s[n][0])[q] = ((const uint4*)wlp)[n * 64 + kb0 * 2 + q];
        }
        __syncthreads();

        #pragma unroll
        for (int kbl = 0; kbl < 2; kbl++) {
            const int k8 = kbl * 8;
            uint32_t ah[2][4], al[2][4];
            #pragma unroll
            for (int t = 0; t < 2; t++) {
                const int r0 = warp * 32 + t * 16 + gq;
                float a0 = xs[r0    ][k8 + tq];
                float a1 = xs[r0 + 8][k8 + tq];
                float a2 = xs[r0    ][k8 + tq + 4];
                float a3 = xs[r0 + 8][k8 + tq + 4];
                tf32_split(a0, ah[t][0], al[t][0]);
                tf32_split(a1, ah[t][1], al[t][1]);
                tf32_split(a2, ah[t][2], al[t][2]);
                tf32_split(a3, ah[t][3], al[t][3]);
            }
            #pragma unroll
            for (int nt = 0; nt < 8; nt++) {
                const int n0 = nt * 8 + gq;
                uint2 bh = wh_s[n0][kbl * 4 + tq];
                uint2 bl = wl_s[n0][kbl * 4 + tq];
                mma_tf32(acc[0][nt], ah[0], bh.x, bh.y);
                mma_tf32(acc[0][nt], ah[0], bl.x, bl.y);
                mma_tf32(acc[0][nt], al[0], bh.x, bh.y);
                mma_tf32(acc[1][nt], ah[1], bh.x, bh.y);
                mma_tf32(acc[1][nt], ah[1], bl.x, bl.y);
                mma_tf32(acc[1][nt], al[1], bh.x, bh.y);
            }
        }
        __syncthreads();
    }

    #pragma unroll
    for (int t = 0; t < 2; t++) {
        const int r_lo = row_base + warp * 32 + t * 16 + gq;
        const int r_hi = r_lo + 8;
        #pragma unroll
        for (int nt = 0; nt < 8; nt++) {
            int c0 = nt * 8 + tq * 2;
            float bx = bias[c0], by = bias[c0 + 1];
            if (r_lo < N_NODES) {
                float2 v = make_float2(acc[t][nt][0] + bx, acc[t][nt][1] + by);
                *(float2*)&support[(size_t)r_lo * D_OUT + c0] = v;
            }
            if (r_hi < N_NODES) {
                float2 v = make_float2(acc[t][nt][2] + bx, acc[t][nt][3] + by);
                *(float2*)&support[(size_t)r_hi * D_OUT + c0] = v;
            }
        }
    }
}

// ---------------------------------------------------------------------------
// Kernel 2: aggregation + LeakyReLU. Full warp per node, 2 edges/iteration.
//   Half-warp h processes edges beg+h, beg+h+2, ...; lane owns 4 columns.
//   Cross-half shfl reduction at the end. No atomics, direct store.
// ---------------------------------------------------------------------------
__global__ __launch_bounds__(256) void agg_node_kernel(
    const int*    __restrict__ edge_src,
    const float*  __restrict__ edge_val,
    const int*    __restrict__ rowptr,
    const float4* __restrict__ support4,
    float4*       __restrict__ out4)
{
    const int node = (blockIdx.x * blockDim.x + threadIdx.x) >> 5;
    const int lane = threadIdx.x & 31;
    if (node >= N_NODES) return;
    const int half = lane >> 4;      // 0 or 1
    const int c4   = lane & 15;      // float4 column

    const int beg = __ldg(&rowptr[node]);
    const int end = __ldg(&rowptr[node + 1]);

    float4 acc = make_float4(0.f, 0.f, 0.f, 0.f);
    #pragma unroll 4
    for (int e = beg + half; e < end; e += 2) {
        const int   s = __ldg(&edge_src[e]);     // uniform within half-warp
        const float v = __ldg(&edge_val[e]);
        float4 sv = __ldg(&support4[(size_t)s * 16 + c4]);
        acc.x += v * sv.x;
        acc.y += v * sv.y;
        acc.z += v * sv.z;
        acc.w += v * sv.w;
    }
    // cross-half reduction: lane i += lane i+16
    acc.x += __shfl_down_sync(0xffffffff, acc.x, 16);
    acc.y += __shfl_down_sync(0xffffffff, acc.y, 16);
    acc.z += __shfl_down_sync(0xffffffff, acc.z, 16);
    acc.w += __shfl_down_sync(0xffffffff, acc.w, 16);

    if (half == 0) {
        acc.x = (acc.x >= 0.f) ? acc.x : NEG_SLOPE * acc.x;
        acc.y = (acc.y >= 0.f) ? acc.y : NEG_SLOPE * acc.y;
        acc.z = (acc.z >= 0.f) ? acc.z : NEG_SLOPE * acc.z;
        acc.w = (acc.w >= 0.f) ? acc.w : NEG_SLOPE * acc.w;
        out4[(size_t)node * 16 + c4] = acc;
    }
}

// ---------------------------------------------------------------------------
// Launch
// ---------------------------------------------------------------------------
extern "C" void kernel_launch(void* const* d_in, const int* in_sizes, int n_in,
                              void* d_out, int out_size) {
    const float* x        = (const float*)d_in[0];
    const float* W        = (const float*)d_in[1];
    const float* b        = (const float*)d_in[2];
    const int*   edge_src = (const int*)  d_in[3];
    const int*   edge_dst = (const int*)  d_in[4];
    const float* edge_val = (const float*)d_in[5];
    float* out = (float*)d_out;

    float* support;
    cudaGetSymbolAddress((void**)&support, g_support);
    int* rowptr;
    cudaGetSymbolAddress((void**)&rowptr, g_rowptr);
    uint2* whp;
    cudaGetSymbolAddress((void**)&whp, g_whp);
    uint2* wlp;
    cudaGetSymbolAddress((void**)&wlp, g_wlp);

    // 0a. W tf32 split (paired layout)
    wsplit_kernel<<<32, 256>>>(W, whp, wlp);

    // 0b. vectorized rowptr (thread per 4 edges)
    rowptr4_kernel<<<(N_EDGES / 4 + 255) / 256, 256>>>(edge_dst, rowptr);

    // 1. tf32 tensor-core projection
    gemm_tf32_kernel<<<(N_NODES + 127) / 128, 128>>>(x, whp, wlp, b, support);

    // 2. fused aggregation + LeakyReLU (warp per node, dual-edge)
    const int n_blocks = (N_NODES * 32 + 255) / 256;
    agg_node_kernel<<<n_blocks, 256>>>(edge_src, edge_val, rowptr,
                                       (const float4*)support, (float4*)out);
}

// round 8
// speedup vs baseline: 1.1653x; 1.1653x over previous
#include <cuda_runtime.h>
#include <cstdint>

#define N_NODES 50000
#define N_EDGES 800000
#define D_IN    256
#define D_OUT   64
#define NEG_SLOPE 0.2f

// Scratch: support = x @ W^T + b   [N_NODES, D_OUT]
__device__ float g_support[N_NODES * D_OUT];
// CSR row pointers for sorted edge_dst
__device__ int g_rowptr[N_NODES + 1];
// W tf32 splits, fragment-paired: [n][kb][tq] -> uint2{w[kb*8+tq], w[kb*8+tq+4]}
__device__ uint2 g_whp[D_OUT * (D_IN / 8) * 4];   // 8192 uint2
__device__ uint2 g_wlp[D_OUT * (D_IN / 8) * 4];

// ---------------------------------------------------------------------------
// TF32 helpers
// ---------------------------------------------------------------------------
__device__ __forceinline__ void tf32_split(float f, uint32_t& hi, uint32_t& lo) {
    uint32_t h;
    asm("cvt.rna.tf32.f32 %0, %1;" : "=r"(h) : "f"(f));
    float hf = __uint_as_float(h);
    float lf = f - hf;
    asm("cvt.rna.tf32.f32 %0, %1;" : "=r"(lo) : "f"(lf));
    hi = h;
}

__device__ __forceinline__ uint32_t tf32_of(float f) {
    uint32_t h;
    asm("cvt.rna.tf32.f32 %0, %1;" : "=r"(h) : "f"(f));
    return h;
}

__device__ __forceinline__ void mma_tf32(float c[4], const uint32_t a[4], uint32_t b0, uint32_t b1) {
    asm volatile(
        "mma.sync.aligned.m16n8k8.row.col.f32.tf32.tf32.f32 "
        "{%0,%1,%2,%3}, {%4,%5,%6,%7}, {%8,%9}, {%0,%1,%2,%3};"
        : "+f"(c[0]), "+f"(c[1]), "+f"(c[2]), "+f"(c[3])
        : "r"(a[0]), "r"(a[1]), "r"(a[2]), "r"(a[3]), "r"(b0), "r"(b1));
}

__device__ __forceinline__ void cp16(void* smem_dst, const void* gmem_src, bool valid) {
    uint32_t d = (uint32_t)__cvta_generic_to_shared(smem_dst);
    int sz = valid ? 16 : 0;
    asm volatile("cp.async.cg.shared.global [%0], [%1], 16, %2;"
                 :: "r"(d), "l"(gmem_src), "r"(sz));
}

// ---------------------------------------------------------------------------
// Kernel 0a: W tf32 split into fragment-paired layout (8192 threads, tiny)
// ---------------------------------------------------------------------------
__global__ void wsplit_kernel(const float* __restrict__ W,
                              uint2* __restrict__ whp,
                              uint2* __restrict__ wlp) {
    int e = blockIdx.x * blockDim.x + threadIdx.x;
    if (e >= D_OUT * (D_IN / 8) * 4) return;
    int n   = e >> 7;        // 0..63
    int rem = e & 127;
    int kb  = rem >> 2;      // 0..31
    int tq  = rem & 3;       // 0..3
    float w0 = __ldg(&W[n * D_IN + kb * 8 + tq]);
    float w1 = __ldg(&W[n * D_IN + kb * 8 + tq + 4]);
    uint32_t h0, l0, h1, l1;
    tf32_split(w0, h0, l0);
    tf32_split(w1, h1, l1);
    whp[e] = make_uint2(h0, h1);
    wlp[e] = make_uint2(l0, l1);
}

// ---------------------------------------------------------------------------
// Kernel 0b: vectorized CSR rowptr from sorted edge_dst (thread per 4 edges)
// ---------------------------------------------------------------------------
__global__ void rowptr4_kernel(const int* __restrict__ edge_dst,
                               int* __restrict__ rowptr) {
    int i = blockIdx.x * blockDim.x + threadIdx.x;   // quad index
    if (i >= N_EDGES / 4) return;
    const int e0 = i * 4;
    int4 d = __ldg((const int4*)&edge_dst[e0]);
    int prev;
    if (e0 == 0) {
        prev = -1;
    } else {
        prev = __ldg(&edge_dst[e0 - 1]);
    }
    int dd[4] = {d.x, d.y, d.z, d.w};
    #pragma unroll
    for (int j = 0; j < 4; j++) {
        for (int n = prev + 1; n <= dd[j]; n++) rowptr[n] = e0 + j;
        prev = dd[j];
    }
    if (e0 + 4 == N_EDGES) {
        for (int n = prev + 1; n <= N_NODES; n++) rowptr[n] = N_EDGES;
    }
}

// ---------------------------------------------------------------------------
// Kernel 1: support = x @ (Whi+Wlo)^T + b  — A rounded to tf32, B fp32-exact.
//   2 mma terms per fragment: ah*bh + ah*bl. cp.async double-buffered.
//   Block: 128 threads (4 warps), 128 rows. Warp: 32 rows x 64 cols.
//   smem: xs 2*10.2KB + wh/wl 2*(5.1+5.1)KB = 41 KB.
// ---------------------------------------------------------------------------
#define KC 16
#define NCHUNK (D_IN / KC)   // 16

__global__ __launch_bounds__(128) void gemm_tf32_kernel(
    const float* __restrict__ x,
    const uint2* __restrict__ whp,
    const uint2* __restrict__ wlp,
    const float* __restrict__ bias,
    float* __restrict__ support)
{
    __shared__ float xs[2][128][20];    // stride 20 words: conflict-free A reads
    __shared__ uint2 wh_s[2][64][10];   // stride 10 uint2 = 20 words: conflict-free B reads
    __shared__ uint2 wl_s[2][64][10];

    const int tid  = threadIdx.x;
    const int warp = tid >> 5;    // 0..3
    const int lane = tid & 31;
    const int gq   = lane >> 2;   // 0..7
    const int tq   = lane & 3;    // 0..3
    const int row_base = blockIdx.x * 128;

    float acc[2][8][4];
    #pragma unroll
    for (int t = 0; t < 2; t++)
        #pragma unroll
        for (int nt = 0; nt < 8; nt++)
            #pragma unroll
            for (int j = 0; j < 4; j++) acc[t][nt][j] = 0.f;

    // --- staging lambda (inlined manually) ---
    // x chunk: 512 float4; 4 per thread. W chunk: 256+256 uint4; 2+2 per thread.
    const int xr  = tid >> 2;          // base row for x staging (r = xr + i*32)
    const int xc4 = tid & 3;
    const int wn  = tid >> 2;          // base n for W staging
    const int wq  = tid & 3;

    // prologue: stage chunk 0 into buf 0
    {
        const int kt = 0, kb0 = 0;
        #pragma unroll
        for (int i = 0; i < 4; i++) {
            int r  = xr + i * 32;
            int gr = row_base + r;
            bool valid = gr < N_NODES;
            cp16(&xs[0][r][xc4 * 4], &x[(size_t)(valid ? gr : 0) * D_IN + kt + xc4 * 4], valid);
        }
        #pragma unroll
        for (int i = 0; i < 2; i++) {
            int n = wn + i * 32;
            cp16(&wh_s[0][n][wq * 2], &((const uint4*)whp)[n * 64 + kb0 * 2 + wq], true);
            cp16(&wl_s[0][n][wq * 2], &((const uint4*)wlp)[n * 64 + kb0 * 2 + wq], true);
        }
        asm volatile("cp.async.commit_group;" ::: "memory");
    }

    int buf = 0;
    for (int c = 0; c < NCHUNK; c++) {
        // stage next chunk into buf^1 (overlaps this chunk's compute)
        if (c + 1 < NCHUNK) {
            const int kt = (c + 1) * KC;
            const int kb0 = kt >> 3;
            #pragma unroll
            for (int i = 0; i < 4; i++) {
                int r  = xr + i * 32;
                int gr = row_base + r;
                bool valid = gr < N_NODES;
                cp16(&xs[buf ^ 1][r][xc4 * 4], &x[(size_t)(valid ? gr : 0) * D_IN + kt + xc4 * 4], valid);
            }
            #pragma unroll
            for (int i = 0; i < 2; i++) {
                int n = wn + i * 32;
                cp16(&wh_s[buf ^ 1][n][wq * 2], &((const uint4*)whp)[n * 64 + kb0 * 2 + wq], true);
                cp16(&wl_s[buf ^ 1][n][wq * 2], &((const uint4*)wlp)[n * 64 + kb0 * 2 + wq], true);
            }
            asm volatile("cp.async.commit_group;" ::: "memory");
            asm volatile("cp.async.wait_group 1;" ::: "memory");
        } else {
            asm volatile("cp.async.wait_group 0;" ::: "memory");
        }
        __syncthreads();

        // compute chunk c from buf
        #pragma unroll
        for (int kbl = 0; kbl < 2; kbl++) {
            const int k8 = kbl * 8;
            uint32_t ah[2][4];
            #pragma unroll
            for (int t = 0; t < 2; t++) {
                const int r0 = warp * 32 + t * 16 + gq;
                ah[t][0] = tf32_of(xs[buf][r0    ][k8 + tq]);
                ah[t][1] = tf32_of(xs[buf][r0 + 8][k8 + tq]);
                ah[t][2] = tf32_of(xs[buf][r0    ][k8 + tq + 4]);
                ah[t][3] = tf32_of(xs[buf][r0 + 8][k8 + tq + 4]);
            }
            #pragma unroll
            for (int nt = 0; nt < 8; nt++) {
                const int n0 = nt * 8 + gq;
                uint2 bh = wh_s[buf][n0][kbl * 4 + tq];
                uint2 bl = wl_s[buf][n0][kbl * 4 + tq];
                mma_tf32(acc[0][nt], ah[0], bh.x, bh.y);
                mma_tf32(acc[0][nt], ah[0], bl.x, bl.y);
                mma_tf32(acc[1][nt], ah[1], bh.x, bh.y);
                mma_tf32(acc[1][nt], ah[1], bl.x, bl.y);
            }
        }
        __syncthreads();   // all warps done reading buf before it is restaged
        buf ^= 1;
    }

    // Epilogue
    #pragma unroll
    for (int t = 0; t < 2; t++) {
        const int r_lo = row_base + warp * 32 + t * 16 + gq;
        const int r_hi = r_lo + 8;
        #pragma unroll
        for (int nt = 0; nt < 8; nt++) {
            int c0 = nt * 8 + tq * 2;
            float bx = bias[c0], by = bias[c0 + 1];
            if (r_lo < N_NODES) {
                float2 v = make_float2(acc[t][nt][0] + bx, acc[t][nt][1] + by);
                *(float2*)&support[(size_t)r_lo * D_OUT + c0] = v;
            }
            if (r_hi < N_NODES) {
                float2 v = make_float2(acc[t][nt][2] + bx, acc[t][nt][3] + by);
                *(float2*)&support[(size_t)r_hi * D_OUT + c0] = v;
            }
        }
    }
}

// ---------------------------------------------------------------------------
// Kernel 2: aggregation + LeakyReLU. Half-warp per node, float4 lanes.
//   (R6 version — best measured total.) No atomics, direct store.
// ---------------------------------------------------------------------------
__global__ __launch_bounds__(256) void agg_node_kernel(
    const int*    __restrict__ edge_src,
    const float*  __restrict__ edge_val,
    const int*    __restrict__ rowptr,
    const float4* __restrict__ support4,
    float4*       __restrict__ out4)
{
    const int warpid = (blockIdx.x * blockDim.x + threadIdx.x) >> 5;
    const int lane   = threadIdx.x & 31;
    const int node   = warpid * 2 + (lane >> 4);
    const int c4     = lane & 15;
    if (node >= N_NODES) return;

    const int beg = __ldg(&rowptr[node]);
    const int end = __ldg(&rowptr[node + 1]);

    float4 acc = make_float4(0.f, 0.f, 0.f, 0.f);
    #pragma unroll 4
    for (int e = beg; e < end; e++) {
        const int   s = __ldg(&edge_src[e]);     // uniform within half-warp
        const float v = __ldg(&edge_val[e]);
        float4 sv = __ldg(&support4[(size_t)s * 16 + c4]);
        acc.x += v * sv.x;
        acc.y += v * sv.y;
        acc.z += v * sv.z;
        acc.w += v * sv.w;
    }
    acc.x = (acc.x >= 0.f) ? acc.x : NEG_SLOPE * acc.x;
    acc.y = (acc.y >= 0.f) ? acc.y : NEG_SLOPE * acc.y;
    acc.z = (acc.z >= 0.f) ? acc.z : NEG_SLOPE * acc.z;
    acc.w = (acc.w >= 0.f) ? acc.w : NEG_SLOPE * acc.w;
    out4[(size_t)node * 16 + c4] = acc;
}

// ---------------------------------------------------------------------------
// Launch
// ---------------------------------------------------------------------------
extern "C" void kernel_launch(void* const* d_in, const int* in_sizes, int n_in,
                              void* d_out, int out_size) {
    const float* x        = (const float*)d_in[0];
    const float* W        = (const float*)d_in[1];
    const float* b        = (const float*)d_in[2];
    const int*   edge_src = (const int*)  d_in[3];
    const int*   edge_dst = (const int*)  d_in[4];
    const float* edge_val = (const float*)d_in[5];
    float* out = (float*)d_out;

    float* support;
    cudaGetSymbolAddress((void**)&support, g_support);
    int* rowptr;
    cudaGetSymbolAddress((void**)&rowptr, g_rowptr);
    uint2* whp;
    cudaGetSymbolAddress((void**)&whp, g_whp);
    uint2* wlp;
    cudaGetSymbolAddress((void**)&wlp, g_wlp);

    // 0a. W tf32 split (paired layout)
    wsplit_kernel<<<32, 256>>>(W, whp, wlp);

    // 0b. vectorized rowptr (thread per 4 edges)
    rowptr4_kernel<<<(N_EDGES / 4 + 255) / 256, 256>>>(edge_dst, rowptr);

    // 1. tf32 tensor-core projection (A tf32, B exact-split, pipelined)
    gemm_tf32_kernel<<<(N_NODES + 127) / 128, 128>>>(x, whp, wlp, b, support);

    // 2. fused aggregation + LeakyReLU (half-warp per node)
    const int n_warps  = (N_NODES + 1) / 2;            // 25000
    const int n_blocks = (n_warps * 32 + 255) / 256;   // 3125
    agg_node_kernel<<<n_blocks, 256>>>(edge_src, edge_val, rowptr,
                                       (const float4*)support, (float4*)out);
}

// round 9
// speedup vs baseline: 1.5528x; 1.3326x over previous
#include <cuda_runtime.h>
#include <cuda_fp16.h>
#include <cstdint>

#define N_NODES 50000
#define N_EDGES 800000
#define D_IN    256
#define D_OUT   64
#define NEG_SLOPE 0.2f

// Scratch: support = x @ W^T + b  stored as fp16  [N_NODES, D_OUT]
__device__ __half g_support[N_NODES * D_OUT];
// CSR row pointers for sorted edge_dst
__device__ int g_rowptr[N_NODES + 1];
// W rounded to tf32, fragment-paired: [n][kb][tq] -> uint2{w[kb*8+tq], w[kb*8+tq+4]}
__device__ uint2 g_whp[D_OUT * (D_IN / 8) * 4];   // 8192 uint2

// ---------------------------------------------------------------------------
// TF32 helpers
// ---------------------------------------------------------------------------
__device__ __forceinline__ uint32_t tf32_of(float f) {
    uint32_t h;
    asm("cvt.rna.tf32.f32 %0, %1;" : "=r"(h) : "f"(f));
    return h;
}

__device__ __forceinline__ void mma_tf32(float c[4], const uint32_t a[4], uint32_t b0, uint32_t b1) {
    asm volatile(
        "mma.sync.aligned.m16n8k8.row.col.f32.tf32.tf32.f32 "
        "{%0,%1,%2,%3}, {%4,%5,%6,%7}, {%8,%9}, {%0,%1,%2,%3};"
        : "+f"(c[0]), "+f"(c[1]), "+f"(c[2]), "+f"(c[3])
        : "r"(a[0]), "r"(a[1]), "r"(a[2]), "r"(a[3]), "r"(b0), "r"(b1));
}

__device__ __forceinline__ void cp16(void* smem_dst, const void* gmem_src, bool valid) {
    uint32_t d = (uint32_t)__cvta_generic_to_shared(smem_dst);
    int sz = valid ? 16 : 0;
    asm volatile("cp.async.cg.shared.global [%0], [%1], 16, %2;"
                 :: "r"(d), "l"(gmem_src), "r"(sz));
}

// ---------------------------------------------------------------------------
// Kernel 0a: round W to tf32, fragment-paired layout (8192 threads, tiny)
// ---------------------------------------------------------------------------
__global__ void wsplit_kernel(const float* __restrict__ W,
                              uint2* __restrict__ whp) {
    int e = blockIdx.x * blockDim.x + threadIdx.x;
    if (e >= D_OUT * (D_IN / 8) * 4) return;
    int n   = e >> 7;        // 0..63
    int rem = e & 127;
    int kb  = rem >> 2;      // 0..31
    int tq  = rem & 3;       // 0..3
    float w0 = __ldg(&W[n * D_IN + kb * 8 + tq]);
    float w1 = __ldg(&W[n * D_IN + kb * 8 + tq + 4]);
    whp[e] = make_uint2(tf32_of(w0), tf32_of(w1));
}

// ---------------------------------------------------------------------------
// Kernel 0b: vectorized CSR rowptr from sorted edge_dst (thread per 4 edges)
// ---------------------------------------------------------------------------
__global__ void rowptr4_kernel(const int* __restrict__ edge_dst,
                               int* __restrict__ rowptr) {
    int i = blockIdx.x * blockDim.x + threadIdx.x;   // quad index
    if (i >= N_EDGES / 4) return;
    const int e0 = i * 4;
    int4 d = __ldg((const int4*)&edge_dst[e0]);
    int prev;
    if (e0 == 0) {
        prev = -1;
    } else {
        prev = __ldg(&edge_dst[e0 - 1]);
    }
    int dd[4] = {d.x, d.y, d.z, d.w};
    #pragma unroll
    for (int j = 0; j < 4; j++) {
        for (int n = prev + 1; n <= dd[j]; n++) rowptr[n] = e0 + j;
        prev = dd[j];
    }
    if (e0 + 4 == N_EDGES) {
        for (int n = prev + 1; n <= N_NODES; n++) rowptr[n] = N_EDGES;
    }
}

// ---------------------------------------------------------------------------
// Kernel 1: support = x @ tf32(W)^T + b  (single tf32 term; A tf32 in-kernel).
//   cp.async double-buffered. Block: 128 threads (4 warps), 128 rows.
//   Warp: 32 rows x 64 cols. smem: xs 2*10.2KB + wh 2*6.1KB = 32.7 KB.
//   Output written as fp16 (half2 pairs).
// ---------------------------------------------------------------------------
#define KC 16
#define NCHUNK (D_IN / KC)   // 16

__global__ __launch_bounds__(128) void gemm_tf32_kernel(
    const float* __restrict__ x,
    const uint2* __restrict__ whp,
    const float* __restrict__ bias,
    __half* __restrict__ support)
{
    __shared__ float xs[2][128][20];    // stride 20 words: conflict-free 32-bit A reads
    __shared__ uint2 wh_s[2][64][12];   // stride 12 uint2: conflict-free LDS.64 (16-lane phases)

    const int tid  = threadIdx.x;
    const int warp = tid >> 5;    // 0..3
    const int lane = tid & 31;
    const int gq   = lane >> 2;   // 0..7
    const int tq   = lane & 3;    // 0..3
    const int row_base = blockIdx.x * 128;

    float acc[2][8][4];
    #pragma unroll
    for (int t = 0; t < 2; t++)
        #pragma unroll
        for (int nt = 0; nt < 8; nt++)
            #pragma unroll
            for (int j = 0; j < 4; j++) acc[t][nt][j] = 0.f;

    const int xr  = tid >> 2;          // base row for x staging
    const int xc4 = tid & 3;
    const int wn  = tid >> 2;          // base n for W staging (0..31)
    const int wq  = tid & 3;

    // prologue: stage chunk 0 into buf 0
    {
        #pragma unroll
        for (int i = 0; i < 4; i++) {
            int r  = xr + i * 32;
            int gr = row_base + r;
            bool valid = gr < N_NODES;
            cp16(&xs[0][r][xc4 * 4], &x[(size_t)(valid ? gr : 0) * D_IN + xc4 * 4], valid);
        }
        #pragma unroll
        for (int i = 0; i < 2; i++) {
            int n = wn + i * 32;
            cp16(&wh_s[0][n][wq * 2], &((const uint4*)whp)[n * 64 + wq], true);
        }
        asm volatile("cp.async.commit_group;" ::: "memory");
    }

    int buf = 0;
    for (int c = 0; c < NCHUNK; c++) {
        if (c + 1 < NCHUNK) {
            const int kt = (c + 1) * KC;
            const int kb0 = kt >> 3;
            #pragma unroll
            for (int i = 0; i < 4; i++) {
                int r  = xr + i * 32;
                int gr = row_base + r;
                bool valid = gr < N_NODES;
                cp16(&xs[buf ^ 1][r][xc4 * 4], &x[(size_t)(valid ? gr : 0) * D_IN + kt + xc4 * 4], valid);
            }
            #pragma unroll
            for (int i = 0; i < 2; i++) {
                int n = wn + i * 32;
                cp16(&wh_s[buf ^ 1][n][wq * 2], &((const uint4*)whp)[n * 64 + kb0 * 2 + wq], true);
            }
            asm volatile("cp.async.commit_group;" ::: "memory");
            asm volatile("cp.async.wait_group 1;" ::: "memory");
        } else {
            asm volatile("cp.async.wait_group 0;" ::: "memory");
        }
        __syncthreads();

        #pragma unroll
        for (int kbl = 0; kbl < 2; kbl++) {
            const int k8 = kbl * 8;
            uint32_t ah[2][4];
            #pragma unroll
            for (int t = 0; t < 2; t++) {
                const int r0 = warp * 32 + t * 16 + gq;
                ah[t][0] = tf32_of(xs[buf][r0    ][k8 + tq]);
                ah[t][1] = tf32_of(xs[buf][r0 + 8][k8 + tq]);
                ah[t][2] = tf32_of(xs[buf][r0    ][k8 + tq + 4]);
                ah[t][3] = tf32_of(xs[buf][r0 + 8][k8 + tq + 4]);
            }
            #pragma unroll
            for (int nt = 0; nt < 8; nt++) {
                const int n0 = nt * 8 + gq;
                uint2 bh = wh_s[buf][n0][kbl * 4 + tq];
                mma_tf32(acc[0][nt], ah[0], bh.x, bh.y);
                mma_tf32(acc[1][nt], ah[1], bh.x, bh.y);
            }
        }
        __syncthreads();
        buf ^= 1;
    }

    // Epilogue: +bias, convert to half2, store (support row = 32 half2)
    __half2* sup2 = (__half2*)support;
    #pragma unroll
    for (int t = 0; t < 2; t++) {
        const int r_lo = row_base + warp * 32 + t * 16 + gq;
        const int r_hi = r_lo + 8;
        #pragma unroll
        for (int nt = 0; nt < 8; nt++) {
            int c0 = nt * 8 + tq * 2;
            float bx = bias[c0], by = bias[c0 + 1];
            int h2 = nt * 4 + tq;   // half2 index within row
            if (r_lo < N_NODES)
                sup2[(size_t)r_lo * 32 + h2] = __floats2half2_rn(acc[t][nt][0] + bx, acc[t][nt][1] + by);
            if (r_hi < N_NODES)
                sup2[(size_t)r_hi * 32 + h2] = __floats2half2_rn(acc[t][nt][2] + bx, acc[t][nt][3] + by);
        }
    }
}

// ---------------------------------------------------------------------------
// Kernel 2: aggregation + LeakyReLU. Half-warp per node, fp16 gather.
//   Lane owns 4 columns (one uint2 = 2 half2); warp handles 2 nodes.
//   No atomics, direct fp32 store.
// ---------------------------------------------------------------------------
__global__ __launch_bounds__(256) void agg_node_kernel(
    const int*   __restrict__ edge_src,
    const float* __restrict__ edge_val,
    const int*   __restrict__ rowptr,
    const uint2* __restrict__ support2,   // fp16 rows: 16 uint2 each
    float4*      __restrict__ out4)
{
    const int warpid = (blockIdx.x * blockDim.x + threadIdx.x) >> 5;
    const int lane   = threadIdx.x & 31;
    const int node   = warpid * 2 + (lane >> 4);
    const int c4     = lane & 15;
    if (node >= N_NODES) return;

    const int beg = __ldg(&rowptr[node]);
    const int end = __ldg(&rowptr[node + 1]);

    float4 acc = make_float4(0.f, 0.f, 0.f, 0.f);
    #pragma unroll 4
    for (int e = beg; e < end; e++) {
        const int   s = __ldg(&edge_src[e]);     // uniform within half-warp
        const float v = __ldg(&edge_val[e]);
        uint2 raw = __ldg(&support2[(size_t)s * 16 + c4]);
        float2 f0 = __half22float2(*(__half2*)&raw.x);
        float2 f1 = __half22float2(*(__half2*)&raw.y);
        acc.x += v * f0.x;
        acc.y += v * f0.y;
        acc.z += v * f1.x;
        acc.w += v * f1.y;
    }
    acc.x = (acc.x >= 0.f) ? acc.x : NEG_SLOPE * acc.x;
    acc.y = (acc.y >= 0.f) ? acc.y : NEG_SLOPE * acc.y;
    acc.z = (acc.z >= 0.f) ? acc.z : NEG_SLOPE * acc.z;
    acc.w = (acc.w >= 0.f) ? acc.w : NEG_SLOPE * acc.w;
    out4[(size_t)node * 16 + c4] = acc;
}

// ---------------------------------------------------------------------------
// Launch
// ---------------------------------------------------------------------------
extern "C" void kernel_launch(void* const* d_in, const int* in_sizes, int n_in,
                              void* d_out, int out_size) {
    const float* x        = (const float*)d_in[0];
    const float* W        = (const float*)d_in[1];
    const float* b        = (const float*)d_in[2];
    const int*   edge_src = (const int*)  d_in[3];
    const int*   edge_dst = (const int*)  d_in[4];
    const float* edge_val = (const float*)d_in[5];
    float* out = (float*)d_out;

    __half* support;
    cudaGetSymbolAddress((void**)&support, g_support);
    int* rowptr;
    cudaGetSymbolAddress((void**)&rowptr, g_rowptr);
    uint2* whp;
    cudaGetSymbolAddress((void**)&whp, g_whp);

    // 0a. W -> tf32 paired layout
    wsplit_kernel<<<32, 256>>>(W, whp);

    // 0b. vectorized rowptr (thread per 4 edges)
    rowptr4_kernel<<<(N_EDGES / 4 + 255) / 256, 256>>>(edge_dst, rowptr);

    // 1. tf32 tensor-core projection -> fp16 support
    gemm_tf32_kernel<<<(N_NODES + 127) / 128, 128>>>(x, whp, b, support);

    // 2. fused aggregation + LeakyReLU (half-warp per node, fp16 gather)
    const int n_warps  = (N_NODES + 1) / 2;            // 25000
    const int n_blocks = (n_warps * 32 + 255) / 256;   // 3125
    agg_node_kernel<<<n_blocks, 256>>>(edge_src, edge_val, rowptr,
                                       (const uint2*)support, (float4*)out);
}

// round 10
// speedup vs baseline: 1.9258x; 1.2401x over previous
#include <cuda_runtime.h>
#include <cuda_fp16.h>
#include <cstdint>

#define N_NODES 50000
#define N_EDGES 800000
#define D_IN    256
#define D_OUT   64
#define NEG_SLOPE 0.2f

// Scratch: support = x @ W^T + b  stored as fp16  [N_NODES, D_OUT]
__device__ __half g_support[N_NODES * D_OUT];
// CSR row pointers for sorted edge_dst
__device__ int g_rowptr[N_NODES + 1];
// W as fp16 B-fragment pairs: [n][kb16][tq] -> uint2{ h2(W[n][16kb+2tq],W[..+1]),
//                                                     h2(W[n][16kb+2tq+8],W[..+9]) }
__device__ uint2 g_whp[D_OUT * (D_IN / 16) * 4];   // 4096 uint2

// ---------------------------------------------------------------------------
// fp16 m16n8k16 mma
// ---------------------------------------------------------------------------
__device__ __forceinline__ void mma_f16(float c[4], const uint32_t a[4], uint32_t b0, uint32_t b1) {
    asm volatile(
        "mma.sync.aligned.m16n8k16.row.col.f32.f16.f16.f32 "
        "{%0,%1,%2,%3}, {%4,%5,%6,%7}, {%8,%9}, {%0,%1,%2,%3};"
        : "+f"(c[0]), "+f"(c[1]), "+f"(c[2]), "+f"(c[3])
        : "r"(a[0]), "r"(a[1]), "r"(a[2]), "r"(a[3]), "r"(b0), "r"(b1));
}

__device__ __forceinline__ void cp16(void* smem_dst, const void* gmem_src, bool valid) {
    uint32_t d = (uint32_t)__cvta_generic_to_shared(smem_dst);
    int sz = valid ? 16 : 0;
    asm volatile("cp.async.cg.shared.global [%0], [%1], 16, %2;"
                 :: "r"(d), "l"(gmem_src), "r"(sz));
}

__device__ __forceinline__ uint32_t pack_h2(float a, float b) {
    __half2 h = __floats2half2_rn(a, b);
    return *(uint32_t*)&h;
}

// ---------------------------------------------------------------------------
// Kernel 0: fused prep — W fp16 pack (first 4096 threads) + rowptr quads
// ---------------------------------------------------------------------------
__global__ void prep_kernel(const int* __restrict__ edge_dst,
                            int* __restrict__ rowptr,
                            const float* __restrict__ W,
                            uint2* __restrict__ whp) {
    int i = blockIdx.x * blockDim.x + threadIdx.x;

    if (i < D_OUT * (D_IN / 16) * 4) {   // 4096
        int n  = i >> 6;
        int kb = (i >> 2) & 15;
        int tq = i & 3;
        const float* wr = &W[n * D_IN + kb * 16];
        uint2 v;
        v.x = pack_h2(__ldg(&wr[2 * tq]),     __ldg(&wr[2 * tq + 1]));
        v.y = pack_h2(__ldg(&wr[2 * tq + 8]), __ldg(&wr[2 * tq + 9]));
        whp[i] = v;
    }

    if (i < N_EDGES / 4) {
        const int e0 = i * 4;
        int4 d = __ldg((const int4*)&edge_dst[e0]);
        int prev = (e0 == 0) ? -1 : __ldg(&edge_dst[e0 - 1]);
        int dd[4] = {d.x, d.y, d.z, d.w};
        #pragma unroll
        for (int j = 0; j < 4; j++) {
            for (int n = prev + 1; n <= dd[j]; n++) rowptr[n] = e0 + j;
            prev = dd[j];
        }
        if (e0 + 4 == N_EDGES) {
            for (int n = prev + 1; n <= N_NODES; n++) rowptr[n] = N_EDGES;
        }
    }
}

// ---------------------------------------------------------------------------
// Kernel 1: support = x @ W^T + b  via fp16 m16n8k16 tensor cores.
//   Block: 128 threads (4 warps), 128 rows. Warp: 32 rows x 64 cols.
//   cp.async double-buffered, K chunks of 16.
//   smem: xs 2*12KB + wh 2*2KB = 28.6 KB. Output fp16.
// ---------------------------------------------------------------------------
#define KC 16
#define NCHUNK (D_IN / KC)   // 16
#define XSTR 24              // word stride: (gq*12+tq) mod 16 all-distinct for float2 reads

__global__ __launch_bounds__(128) void gemm_f16_kernel(
    const float* __restrict__ x,
    const uint2* __restrict__ whp,
    const float* __restrict__ bias,
    __half* __restrict__ support)
{
    __shared__ float xs[2][128][XSTR];
    __shared__ uint2 wh_s[2][64][4];   // stride 4 uint2: conflict-free (gq*4+tq mod 16)

    const int tid  = threadIdx.x;
    const int warp = tid >> 5;    // 0..3
    const int lane = tid & 31;
    const int gq   = lane >> 2;   // 0..7
    const int tq   = lane & 3;    // 0..3
    const int row_base = blockIdx.x * 128;

    float acc[2][8][4];
    #pragma unroll
    for (int t = 0; t < 2; t++)
        #pragma unroll
        for (int nt = 0; nt < 8; nt++)
            #pragma unroll
            for (int j = 0; j < 4; j++) acc[t][nt][j] = 0.f;

    const int xr  = tid >> 2;   // x staging base row
    const int xc4 = tid & 3;
    const int wn  = tid >> 1;   // W staging n (0..63)
    const int wq  = tid & 1;

    // prologue: stage chunk 0 -> buf 0
    {
        #pragma unroll
        for (int i = 0; i < 4; i++) {
            int r  = xr + i * 32;
            int gr = row_base + r;
            bool valid = gr < N_NODES;
            cp16(&xs[0][r][xc4 * 4], &x[(size_t)(valid ? gr : 0) * D_IN + xc4 * 4], valid);
        }
        cp16(&wh_s[0][wn][wq * 2], &((const uint4*)whp)[wn * 32 + wq], true);
        asm volatile("cp.async.commit_group;" ::: "memory");
    }

    int buf = 0;
    for (int c = 0; c < NCHUNK; c++) {
        if (c + 1 < NCHUNK) {
            const int kt = (c + 1) * KC;
            #pragma unroll
            for (int i = 0; i < 4; i++) {
                int r  = xr + i * 32;
                int gr = row_base + r;
                bool valid = gr < N_NODES;
                cp16(&xs[buf ^ 1][r][xc4 * 4], &x[(size_t)(valid ? gr : 0) * D_IN + kt + xc4 * 4], valid);
            }
            cp16(&wh_s[buf ^ 1][wn][wq * 2], &((const uint4*)whp)[wn * 32 + (c + 1) * 2 + wq], true);
            asm volatile("cp.async.commit_group;" ::: "memory");
            asm volatile("cp.async.wait_group 1;" ::: "memory");
        } else {
            asm volatile("cp.async.wait_group 0;" ::: "memory");
        }
        __syncthreads();

        // one m16n8k16 step per tile per nt
        uint32_t a[2][4];
        #pragma unroll
        for (int t = 0; t < 2; t++) {
            const int r0 = warp * 32 + t * 16 + gq;
            float2 p0 = *(const float2*)&xs[buf][r0    ][2 * tq];
            float2 p1 = *(const float2*)&xs[buf][r0 + 8][2 * tq];
            float2 p2 = *(const float2*)&xs[buf][r0    ][2 * tq + 8];
            float2 p3 = *(const float2*)&xs[buf][r0 + 8][2 * tq + 8];
            a[t][0] = pack_h2(p0.x, p0.y);
            a[t][1] = pack_h2(p1.x, p1.y);
            a[t][2] = pack_h2(p2.x, p2.y);
            a[t][3] = pack_h2(p3.x, p3.y);
        }
        #pragma unroll
        for (int nt = 0; nt < 8; nt++) {
            uint2 bb = wh_s[buf][nt * 8 + gq][tq];
            mma_f16(acc[0][nt], a[0], bb.x, bb.y);
            mma_f16(acc[1][nt], a[1], bb.x, bb.y);
        }
        __syncthreads();
        buf ^= 1;
    }

    // Epilogue: +bias, store as half2 (support row = 32 half2)
    __half2* sup2 = (__half2*)support;
    #pragma unroll
    for (int t = 0; t < 2; t++) {
        const int r_lo = row_base + warp * 32 + t * 16 + gq;
        const int r_hi = r_lo + 8;
        #pragma unroll
        for (int nt = 0; nt < 8; nt++) {
            int c0 = nt * 8 + tq * 2;
            float bx = bias[c0], by = bias[c0 + 1];
            int h2 = nt * 4 + tq;
            if (r_lo < N_NODES)
                sup2[(size_t)r_lo * 32 + h2] = __floats2half2_rn(acc[t][nt][0] + bx, acc[t][nt][1] + by);
            if (r_hi < N_NODES)
                sup2[(size_t)r_hi * 32 + h2] = __floats2half2_rn(acc[t][nt][2] + bx, acc[t][nt][3] + by);
        }
    }
}

// ---------------------------------------------------------------------------
// Kernel 2: aggregation + LeakyReLU. 8 lanes per node, LDG.128 fp16 gather.
//   Lane owns 8 columns (one uint4 = 4 half2); warp handles 4 nodes.
//   No atomics, direct fp32 store.
// ---------------------------------------------------------------------------
__global__ __launch_bounds__(256) void agg_node_kernel(
    const int*   __restrict__ edge_src,
    const float* __restrict__ edge_val,
    const int*   __restrict__ rowptr,
    const uint4* __restrict__ support8,   // fp16 rows: 8 uint4 each
    float4*      __restrict__ out4)
{
    const int warpid = (blockIdx.x * blockDim.x + threadIdx.x) >> 5;
    const int lane   = threadIdx.x & 31;
    const int node   = warpid * 4 + (lane >> 3);
    const int c8     = lane & 7;          // uint4 (8-column) slot
    if (node >= N_NODES) return;

    const int beg = __ldg(&rowptr[node]);
    const int end = __ldg(&rowptr[node + 1]);

    float acc[8];
    #pragma unroll
    for (int j = 0; j < 8; j++) acc[j] = 0.f;

    #pragma unroll 4
    for (int e = beg; e < end; e++) {
        const int   s = __ldg(&edge_src[e]);     // uniform within octet
        const float v = __ldg(&edge_val[e]);
        uint4 raw = __ldg(&support8[(size_t)s * 8 + c8]);
        float2 f0 = __half22float2(*(__half2*)&raw.x);
        float2 f1 = __half22float2(*(__half2*)&raw.y);
        float2 f2 = __half22float2(*(__half2*)&raw.z);
        float2 f3 = __half22float2(*(__half2*)&raw.w);
        acc[0] += v * f0.x;  acc[1] += v * f0.y;
        acc[2] += v * f1.x;  acc[3] += v * f1.y;
        acc[4] += v * f2.x;  acc[5] += v * f2.y;
        acc[6] += v * f3.x;  acc[7] += v * f3.y;
    }
    #pragma unroll
    for (int j = 0; j < 8; j++)
        acc[j] = (acc[j] >= 0.f) ? acc[j] : NEG_SLOPE * acc[j];

    const size_t ob = (size_t)node * 16 + c8 * 2;
    out4[ob]     = make_float4(acc[0], acc[1], acc[2], acc[3]);
    out4[ob + 1] = make_float4(acc[4], acc[5], acc[6], acc[7]);
}

// ---------------------------------------------------------------------------
// Launch
// ---------------------------------------------------------------------------
extern "C" void kernel_launch(void* const* d_in, const int* in_sizes, int n_in,
                              void* d_out, int out_size) {
    const float* x        = (const float*)d_in[0];
    const float* W        = (const float*)d_in[1];
    const float* b        = (const float*)d_in[2];
    const int*   edge_src = (const int*)  d_in[3];
    const int*   edge_dst = (const int*)  d_in[4];
    const float* edge_val = (const float*)d_in[5];
    float* out = (float*)d_out;

    __half* support;
    cudaGetSymbolAddress((void**)&support, g_support);
    int* rowptr;
    cudaGetSymbolAddress((void**)&rowptr, g_rowptr);
    uint2* whp;
    cudaGetSymbolAddress((void**)&whp, g_whp);

    // 0. fused prep: W fp16 pack + rowptr
    prep_kernel<<<(N_EDGES / 4 + 255) / 256, 256>>>(edge_dst, rowptr, W, whp);

    // 1. fp16 tensor-core projection -> fp16 support
    gemm_f16_kernel<<<(N_NODES + 127) / 128, 128>>>(x, whp, b, support);

    // 2. fused aggregation + LeakyReLU (8 lanes per node, LDG.128 gather)
    const int n_warps  = (N_NODES + 3) / 4;            // 12500
    const int n_blocks = (n_warps * 32 + 255) / 256;   // 1563
    agg_node_kernel<<<n_blocks, 256>>>(edge_src, edge_val, rowptr,
                                       (const uint4*)support, (float4*)out);
}